// round 11
// baseline (speedup 1.0000x reference)
#include <cuda_runtime.h>
#include <cuda_fp16.h>
#include <math.h>
#include <stdint.h>
#include <mma.h>

using namespace nvcuda;

// Problem constants
#define S_   256
#define B_   128
#define I_   1024
#define H_   512
#define G4  (4 * H_)            // 2048 gate rows of W_ih / gate cols
#define NBLK 128

// ---------------------------------------------------------------------------
// Device scratch (g_G deleted: gates are produced and consumed in-register)
// ---------------------------------------------------------------------------
__device__ float g_h[2][B_ * H_];             // double-buffered hidden state
__device__ int            g_cnt;              // grid barrier arrive counter
__device__ volatile int   g_gen;              // grid barrier generation
__device__ float g_bias_rep[16 * G4];         // bias replicated over 16 rows
__device__ __half g_wih16[(size_t)G4 * I_];   // fp16 copy of w_ih (4 MB, L2-resident)

// ---------------------------------------------------------------------------
// Init: zero h0 and barrier state
// ---------------------------------------------------------------------------
__global__ void init_state() {
    int i = blockIdx.x * blockDim.x + threadIdx.x;
    if (i < B_ * H_) g_h[0][i] = 0.0f;
    if (i == 0) { g_cnt = 0; g_gen = 0; }
}

// ---------------------------------------------------------------------------
// Fill 16-row replicated bias strip (loaded as wmma C fragment, col_major)
// ---------------------------------------------------------------------------
__global__ void fill_bias(const float* __restrict__ bih,
                          const float* __restrict__ bhh) {
    int c = blockIdx.x * blockDim.x + threadIdx.x;
    if (c < G4) {
        float v = bih[c] + bhh[c];
#pragma unroll
        for (int r = 0; r < 16; r++) g_bias_rep[r * G4 + c] = v;
    }
}

// ---------------------------------------------------------------------------
// Convert w_ih fp32 -> fp16 (once)
// ---------------------------------------------------------------------------
__global__ __launch_bounds__(256) void conv_wih(const float* __restrict__ w) {
    int i = (blockIdx.x * blockDim.x + threadIdx.x) * 4;
    if (i < G4 * I_) {
        float4 v = *(const float4*)(w + i);
        __half2 a = __floats2half2_rn(v.x, v.y);
        __half2 b = __floats2half2_rn(v.z, v.w);
        *(uint32_t*)(g_wih16 + i)     = *(uint32_t*)&a;
        *(uint32_t*)(g_wih16 + i + 2) = *(uint32_t*)&b;
    }
}

// ---------------------------------------------------------------------------
// Fused persistent LSTM: per step, per CTA (cg = hidden-col group of 16,
// bg = batch group of 32):
//   gates[64x32] = bias + x[s]@W_ih^T (fp16 single) + h@W_hh^T (h hi/lo fp16
//   2-term vs single fp16 w_hh), all accumulated in ONE wmma C fragment.
// 8 warps = 4 gate-tiles x 2 batch-tiles of 16x16. Input-gemm for step s+1
// runs AFTER the barrier arrive (independent of h) -> barrier latency hidden.
// ---------------------------------------------------------------------------
#define LDW 520                     // halfs; 1040B rows (16B offset pattern, bank-clean)
#define LDX 1032                    // halfs; 2064B rows
#define LDH 520
#define LDC 36                      // floats; 144B rows
#define OFF_WHH 0
#define OFF_X   (64 * LDW * 2)                  // 66560
#define OFF_HHI (OFF_X   + 32 * LDX * 2)        // 132608
#define OFF_HLO (OFF_HHI + 32 * LDH * 2)        // 165888
#define OFF_GT  (OFF_HLO + 32 * LDH * 2)        // 199168
#define FUSED_SMEM (OFF_GT + 64 * LDC * 4)      // 208384 bytes

__global__ __launch_bounds__(256, 1) void lstm_fused(
    const float* __restrict__ X,
    const float* __restrict__ Whh)
{
    extern __shared__ char sm[];
    __half* s_whh = (__half*)(sm + OFF_WHH);
    __half* s_x   = (__half*)(sm + OFF_X);
    __half* s_hhi = (__half*)(sm + OFF_HHI);
    __half* s_hlo = (__half*)(sm + OFF_HLO);
    float*  gt    = (float*)(sm + OFF_GT);

    const int bid = blockIdx.x;
    const int cg  = bid >> 2;       // 0..31: hidden cols [cg*16, cg*16+16)
    const int bg  = bid & 3;        // 0..3 : batches    [bg*32, bg*32+32)
    const int t   = threadIdx.x;
    const int wid = t >> 5;
    const int mt  = wid >> 1;       // 0..3: gate g = mt
    const int nt  = wid & 1;        // 0..1: batch sub-tile

    // ---- stage w_hh tile (64 gate rows x 512) as single fp16, once ----
    {
        const int p  = t >> 2;                  // 0..63; row p <-> j = (p>>4)*H + cg*16 + (p&15)
        const int ks = (t & 3) * 128;
        const int j  = (p >> 4) * H_ + cg * 16 + (p & 15);
        const float* src = Whh + (size_t)j * H_ + ks;
        __half* dst = s_whh + p * LDW + ks;
#pragma unroll 8
        for (int i = 0; i < 128; i += 4) {
            float4 v = *(const float4*)(src + i);
            __half2 h0 = __floats2half2_rn(v.x, v.y);
            __half2 h1 = __floats2half2_rn(v.z, v.w);
            *(uint32_t*)(dst + i)     = *(uint32_t*)&h0;
            *(uint32_t*)(dst + i + 2) = *(uint32_t*)&h1;
        }
    }

    // ---- pointwise cell mapping; c lives in registers ----
    const int cc0 = 2 * t,     cc1 = 2 * t + 1;
    const int nn0 = cc0 >> 5,  bl0 = cc0 & 31;      // hidden-col-within-16, batch-within-32
    const int nn1 = cc1 >> 5,  bl1 = cc1 & 31;
    float creg0 = 0.0f, creg1 = 0.0f;

    // warp's gate-row base in [0,2048): j = mt*512 + cg*16 + m
    const int jw = mt * H_ + cg * 16;
    const float*  biasp = g_bias_rep + jw;           // col_major C load -> bias[jw+m] for all n
    const __half* wgA   = g_wih16 + (size_t)jw * I_; // A frags for input gemm (global, L2)

    wmma::fragment<wmma::accumulator, 16, 16, 16, float> acc;

    __syncthreads();   // w_hh staged

    // ---- prologue: stage x(0) and run input-gemm(0) into acc ----
    {
        const int row = t >> 3, cb = (t & 7) * 128;
        const float* src = X + ((size_t)0 * B_ + bg * 32 + row) * I_ + cb;
        __half* dst = s_x + row * LDX + cb;
#pragma unroll 4
        for (int i = 0; i < 128; i += 8) {
            float4 v0 = *(const float4*)(src + i);
            float4 v1 = *(const float4*)(src + i + 4);
            __half2 a = __floats2half2_rn(v0.x, v0.y);
            __half2 b = __floats2half2_rn(v0.z, v0.w);
            __half2 c = __floats2half2_rn(v1.x, v1.y);
            __half2 d = __floats2half2_rn(v1.z, v1.w);
            *(uint4*)(dst + i) = make_uint4(*(uint32_t*)&a, *(uint32_t*)&b,
                                            *(uint32_t*)&c, *(uint32_t*)&d);
        }
    }
    __syncthreads();
    wmma::load_matrix_sync(acc, biasp, G4, wmma::mem_col_major);
    {
        const __half* xb = s_x + (nt * 16) * LDX;
        wmma::fragment<wmma::matrix_a, 16, 16, 16, __half, wmma::row_major> af[2];
        wmma::load_matrix_sync(af[0], wgA, I_);
#pragma unroll 4
        for (int k = 0; k < 64; k++) {
            if (k < 63)
                wmma::load_matrix_sync(af[(k + 1) & 1], wgA + (k + 1) * 16, I_);
            wmma::fragment<wmma::matrix_b, 16, 16, 16, __half, wmma::col_major> bf;
            wmma::load_matrix_sync(bf, xb + k * 16, LDX);
            wmma::mma_sync(acc, af[k & 1], bf, acc);
        }
    }

    for (int s = 0; s < S_; ++s) {
        // ---- wait for step s-1's h to be globally visible ----
        if (s > 0) {
            if (t == 0) { while (g_gen < s) { } }
            __syncthreads();
            __threadfence();
        }

        // ---- stage h tile (32 x 512) as fp16 hi/lo ----
        {
            const float* h_in = g_h[s & 1];
            const int row = t >> 3, ks = (t & 7) * 64;
            const float* src = h_in + (size_t)(bg * 32 + row) * H_ + ks;
            __half* dh = s_hhi + row * LDH + ks;
            __half* dl = s_hlo + row * LDH + ks;
#pragma unroll 4
            for (int i = 0; i < 64; i += 4) {
                float4 v = *(const float4*)(src + i);
                __half2 h0 = __floats2half2_rn(v.x, v.y);
                __half2 h1 = __floats2half2_rn(v.z, v.w);
                __half2 l0 = __floats2half2_rn(v.x - __half2float(__low2half(h0)),
                                               v.y - __half2float(__high2half(h0)));
                __half2 l1 = __floats2half2_rn(v.z - __half2float(__low2half(h1)),
                                               v.w - __half2float(__high2half(h1)));
                *(uint32_t*)(dh + i)     = *(uint32_t*)&h0;
                *(uint32_t*)(dh + i + 2) = *(uint32_t*)&h1;
                *(uint32_t*)(dl + i)     = *(uint32_t*)&l0;
                *(uint32_t*)(dl + i + 2) = *(uint32_t*)&l1;
            }
        }
        __syncthreads();

        // ---- recurrent GEMM into acc: (h_hi + h_lo) @ w_hh^T, 64 wmma ----
        {
            const __half* wb = s_whh + (mt * 16) * LDW;
            const __half* hb = s_hhi + (nt * 16) * LDH;
            const __half* lb = s_hlo + (nt * 16) * LDH;
#pragma unroll 4
            for (int k = 0; k < 32; k++) {
                wmma::fragment<wmma::matrix_a, 16, 16, 16, __half, wmma::row_major> a;
                wmma::fragment<wmma::matrix_b, 16, 16, 16, __half, wmma::col_major> b0, b1;
                wmma::load_matrix_sync(a,  wb + k * 16, LDW);
                wmma::load_matrix_sync(b0, hb + k * 16, LDH);
                wmma::load_matrix_sync(b1, lb + k * 16, LDH);
                wmma::mma_sync(acc, a, b0, acc);
                wmma::mma_sync(acc, a, b1, acc);
            }
        }
        wmma::store_matrix_sync(gt + (mt * 16) * LDC + nt * 16, acc, LDC,
                                wmma::mem_row_major);
        __syncthreads();

        // ---- pointwise LSTM update (2 cells per thread) ----
        float* h_out = g_h[(s + 1) & 1];
        {
            float gi = gt[(0 * 16 + nn0) * LDC + bl0];
            float gf = gt[(1 * 16 + nn0) * LDC + bl0];
            float gg = gt[(2 * 16 + nn0) * LDC + bl0];
            float go = gt[(3 * 16 + nn0) * LDC + bl0];
            float si = 1.0f / (1.0f + __expf(-gi));
            float sf = 1.0f / (1.0f + __expf(-gf));
            float tg = tanhf(gg);
            float so = 1.0f / (1.0f + __expf(-go));
            creg0 = sf * creg0 + si * tg;
            h_out[(size_t)(bg * 32 + bl0) * H_ + cg * 16 + nn0] = so * tanhf(creg0);
        }
        {
            float gi = gt[(0 * 16 + nn1) * LDC + bl1];
            float gf = gt[(1 * 16 + nn1) * LDC + bl1];
            float gg = gt[(2 * 16 + nn1) * LDC + bl1];
            float go = gt[(3 * 16 + nn1) * LDC + bl1];
            float si = 1.0f / (1.0f + __expf(-gi));
            float sf = 1.0f / (1.0f + __expf(-gf));
            float tg = tanhf(gg);
            float so = 1.0f / (1.0f + __expf(-go));
            creg1 = sf * creg1 + si * tg;
            h_out[(size_t)(bg * 32 + bl1) * H_ + cg * 16 + nn1] = so * tanhf(creg1);
        }

        // ---- arrive at grid barrier, then hide its latency behind the
        //      (h-independent) x staging + input-gemm for step s+1 ----
        __threadfence();
        __syncthreads();
        if (t == 0) {
            int old = atomicAdd(&g_cnt, 1);
            if (old == NBLK - 1) {
                atomicExch(&g_cnt, 0);
                __threadfence();
                g_gen = s + 1;
            }
        }

        if (s + 1 < S_) {
            {
                const int row = t >> 3, cb = (t & 7) * 128;
                const float* src = X + ((size_t)(s + 1) * B_ + bg * 32 + row) * I_ + cb;
                __half* dst = s_x + row * LDX + cb;
#pragma unroll 4
                for (int i = 0; i < 128; i += 8) {
                    float4 v0 = *(const float4*)(src + i);
                    float4 v1 = *(const float4*)(src + i + 4);
                    __half2 a = __floats2half2_rn(v0.x, v0.y);
                    __half2 b = __floats2half2_rn(v0.z, v0.w);
                    __half2 c = __floats2half2_rn(v1.x, v1.y);
                    __half2 d = __floats2half2_rn(v1.z, v1.w);
                    *(uint4*)(dst + i) = make_uint4(*(uint32_t*)&a, *(uint32_t*)&b,
                                                    *(uint32_t*)&c, *(uint32_t*)&d);
                }
            }
            __syncthreads();
            wmma::load_matrix_sync(acc, biasp, G4, wmma::mem_col_major);
            {
                const __half* xb = s_x + (nt * 16) * LDX;
                wmma::fragment<wmma::matrix_a, 16, 16, 16, __half, wmma::row_major> af[2];
                wmma::load_matrix_sync(af[0], wgA, I_);
#pragma unroll 4
                for (int k = 0; k < 64; k++) {
                    if (k < 63)
                        wmma::load_matrix_sync(af[(k + 1) & 1], wgA + (k + 1) * 16, I_);
                    wmma::fragment<wmma::matrix_b, 16, 16, 16, __half, wmma::col_major> bf;
                    wmma::load_matrix_sync(bf, xb + k * 16, LDX);
                    wmma::mma_sync(acc, af[k & 1], bf, acc);
                }
            }
        }
    }
}

// ---------------------------------------------------------------------------
// Final reduction: sum h_final (g_h[0] after 256 steps) -> out[0]
// ---------------------------------------------------------------------------
__global__ __launch_bounds__(1024) void reduce_h(float* __restrict__ out) {
    __shared__ float red[1024];
    const int t = threadIdx.x;
    float s = 0.0f;
    for (int i = t; i < B_ * H_; i += 1024) s += g_h[0][i];
    red[t] = s;
    __syncthreads();
    for (int off = 512; off > 0; off >>= 1) {
        if (t < off) red[t] += red[t + off];
        __syncthreads();
    }
    if (t == 0) out[0] = red[0];
}

// ---------------------------------------------------------------------------
// kernel_launch
// ---------------------------------------------------------------------------
extern "C" void kernel_launch(void* const* d_in, const int* in_sizes, int n_in,
                              void* d_out, int out_size) {
    const float* x    = (const float*)d_in[0];
    const float* w_ih = (const float*)d_in[1];
    const float* w_hh = (const float*)d_in[2];
    const float* b_ih = (const float*)d_in[3];
    const float* b_hh = (const float*)d_in[4];
    float* out = (float*)d_out;

    static_assert(FUSED_SMEM <= 227 * 1024, "smem overflow (fused)");
    cudaFuncSetAttribute(lstm_fused,
                         cudaFuncAttributeMaxDynamicSharedMemorySize,
                         FUSED_SMEM);

    init_state<<<(B_ * H_ + 255) / 256, 256>>>();
    fill_bias<<<(G4 + 255) / 256, 256>>>(b_ih, b_hh);
    conv_wih<<<(G4 * I_ / 4 + 255) / 256, 256>>>(w_ih);

    lstm_fused<<<NBLK, 256, FUSED_SMEM>>>(x, w_hh);

    reduce_h<<<1, 1024>>>(out);
}

// round 13
// speedup vs baseline: 1.4940x; 1.4940x over previous
#include <cuda_runtime.h>
#include <cuda_bf16.h>
#include <cuda_fp16.h>
#include <math.h>
#include <stdint.h>
#include <mma.h>

using namespace nvcuda;

// Problem constants
#define S_   256
#define B_   128
#define I_   1024
#define H_   512
#define G4  (4 * H_)            // 2048 gate columns
#define M_TOT (S_ * B_)         // 32768 rows of the input GEMM
#define NBLK 128

// ---------------------------------------------------------------------------
// Device scratch — total statics kept at the PROVEN ~269 MB budget.
// (Adding large staging arrays beyond this silently corrupts: r3/r5/r12.)
// ---------------------------------------------------------------------------
__device__ float g_G[(size_t)M_TOT * G4];     // x@w_ih^T + bias  (268 MB)
__device__ float g_h[2][B_ * H_];             // double-buffered hidden state
__device__ int            g_cnt;              // grid barrier arrive counter
__device__ volatile int   g_gen;              // grid barrier generation
__device__ float g_bias_rep[16 * G4];         // bias replicated over 16 rows

// ---------------------------------------------------------------------------
// Init: zero h0 and barrier state
// ---------------------------------------------------------------------------
__global__ void init_state() {
    int i = blockIdx.x * blockDim.x + threadIdx.x;
    if (i < B_ * H_) g_h[0][i] = 0.0f;
    if (i == 0) { g_cnt = 0; g_gen = 0; }
}

// ---------------------------------------------------------------------------
// Fill 16-row replicated bias strip (loaded as wmma C fragment)
// ---------------------------------------------------------------------------
__global__ void fill_bias(const float* __restrict__ bih,
                          const float* __restrict__ bhh) {
    int c = blockIdx.x * blockDim.x + threadIdx.x;
    if (c < G4) {
        float v = bih[c] + bhh[c];
#pragma unroll
        for (int r = 0; r < 16; r++) g_bias_rep[r * G4 + c] = v;
    }
}

// ---------------------------------------------------------------------------
// convert 16 fp32 -> 16 fp16, 2 uint4 smem stores
// ---------------------------------------------------------------------------
__device__ __forceinline__ void cvt_store16(
    __half* __restrict__ dst, const float4* v)   // v[0..3]
{
#pragma unroll
    for (int j = 0; j < 2; j++) {
        __half2 a = __floats2half2_rn(v[2*j].x, v[2*j].y);
        __half2 b = __floats2half2_rn(v[2*j].z, v[2*j].w);
        __half2 c = __floats2half2_rn(v[2*j+1].x, v[2*j+1].y);
        __half2 d = __floats2half2_rn(v[2*j+1].z, v[2*j+1].w);
        *(uint4*)(dst + j * 8) = make_uint4(*(uint32_t*)&a, *(uint32_t*)&b,
                                            *(uint32_t*)&c, *(uint32_t*)&d);
    }
}

// ---------------------------------------------------------------------------
// Phase 1: G = X @ W_ih^T + bias, fp16 WMMA.
// Block tile 128m x 256n, grid (8, 256) = 2048 CTAs (halves X redundancy).
// BK=32, double-buffered smem, ONE sync per iteration; staging LDGs issue
// ahead of the MMA stream so global latency hides under HMMA.
// 8 warps (2m x 4n), warp tile 64x64 = 4x4 m16n16k16 frags, 32 wmma/iter.
// Arithmetic bit-identical to R10 (same rn converts, same k-order).
// ---------------------------------------------------------------------------
#define BK   32
#define LDSF 40                 // half row stride (80B, padded)
#define NI   (I_ / BK)          // 32
#define SM_A0 0
#define SM_A1 (128 * LDSF)
#define SM_B0 (2 * 128 * LDSF)
#define SM_B1 (2 * 128 * LDSF + 256 * LDSF)
#define GEMM_SMEM ((2 * 128 * LDSF + 2 * 256 * LDSF) * 2)   // 61440 bytes

__global__ __launch_bounds__(256) void gemm_fp16(
    const float* __restrict__ X,
    const float* __restrict__ W)
{
    extern __shared__ __half sh[];

    const int t   = threadIdx.x;
    const int wid = t >> 5;
    const int m0  = blockIdx.y * 128;
    const int n0  = blockIdx.x * 256;
    const int wr  = wid >> 2;          // 0..1 -> 64 M rows
    const int wc  = wid & 3;           // 0..3 -> 64 N cols

    wmma::fragment<wmma::accumulator, 16, 16, 16, float> acc[4][4];
#pragma unroll
    for (int mt = 0; mt < 4; mt++)
#pragma unroll
        for (int nt = 0; nt < 4; nt++)
            wmma::load_matrix_sync(acc[mt][nt],
                g_bias_rep + n0 + wc * 64 + nt * 16, G4, wmma::mem_row_major);

    // A staging: thread -> (row = t>>1, 16-col half = (t&1)*16)
    const int arow = t >> 1;
    const int acol = (t & 1) * 16;
    const float* gA = X + (size_t)(m0 + arow) * I_ + acol;
    __half* sAd[2] = { sh + SM_A0 + arow * LDSF + acol,
                       sh + SM_A1 + arow * LDSF + acol };
    // B staging: thread -> full 32-col row (row = t)
    const float* gB = W + (size_t)(n0 + t) * I_;
    __half* sBd[2] = { sh + SM_B0 + t * LDSF,
                       sh + SM_B1 + t * LDSF };

    // ---- prologue: stage chunk 0 into buffer 0 ----
    {
        float4 va[4];
#pragma unroll
        for (int j = 0; j < 4; j++) va[j] = *(const float4*)(gA + j * 4);
        cvt_store16(sAd[0], va);
        float4 vb[4];
#pragma unroll
        for (int j = 0; j < 4; j++) vb[j] = *(const float4*)(gB + j * 4);
        cvt_store16(sBd[0], vb);
#pragma unroll
        for (int j = 0; j < 4; j++) vb[j] = *(const float4*)(gB + 16 + j * 4);
        cvt_store16(sBd[0] + 16, vb);
    }
    __syncthreads();

    for (int it = 0; it < NI; ++it) {
        const int cur = it & 1;

        // issue next chunk's staging FIRST (LDG latency hides under MMA)
        if (it + 1 < NI) {
            const int k0 = (it + 1) * BK;
            float4 va[4];
#pragma unroll
            for (int j = 0; j < 4; j++) va[j] = *(const float4*)(gA + k0 + j * 4);
            cvt_store16(sAd[cur ^ 1], va);
            float4 vb[4];
#pragma unroll
            for (int j = 0; j < 4; j++) vb[j] = *(const float4*)(gB + k0 + j * 4);
            cvt_store16(sBd[cur ^ 1], vb);
#pragma unroll
            for (int j = 0; j < 4; j++) vb[j] = *(const float4*)(gB + k0 + 16 + j * 4);
            cvt_store16(sBd[cur ^ 1] + 16, vb);
        }

        // compute on buffer cur: 2 x k16 sub-chunks, 16 wmma each
        const __half* sAc = sh + (cur ? SM_A1 : SM_A0);
        const __half* sBc = sh + (cur ? SM_B1 : SM_B0);
#pragma unroll
        for (int kk = 0; kk < 2; kk++) {
            wmma::fragment<wmma::matrix_a, 16, 16, 16, __half, wmma::row_major> af[4];
#pragma unroll
            for (int mt = 0; mt < 4; mt++)
                wmma::load_matrix_sync(af[mt],
                    sAc + (wr * 64 + mt * 16) * LDSF + kk * 16, LDSF);
#pragma unroll
            for (int nt = 0; nt < 4; nt++) {
                wmma::fragment<wmma::matrix_b, 16, 16, 16, __half, wmma::col_major> bf;
                wmma::load_matrix_sync(bf,
                    sBc + (wc * 64 + nt * 16) * LDSF + kk * 16, LDSF);
#pragma unroll
                for (int mt = 0; mt < 4; mt++)
                    wmma::mma_sync(acc[mt][nt], af[mt], bf, acc[mt][nt]);
            }
        }
        __syncthreads();
    }

#pragma unroll
    for (int mt = 0; mt < 4; mt++)
#pragma unroll
        for (int nt = 0; nt < 4; nt++)
            wmma::store_matrix_sync(
                g_G + (size_t)(m0 + wr * 64 + mt * 16) * G4 + n0 + wc * 64 + nt * 16,
                acc[mt][nt], G4, wmma::mem_row_major);
}

// ---------------------------------------------------------------------------
// Phase 2: persistent LSTM recurrence on tensor cores (verified R8/R10).
// ---------------------------------------------------------------------------
#define LDW 520
#define LDH 520
#define LDC 36
#define OFF_WHI 0
#define OFF_WLO (OFF_WHI + 64 * LDW * 2)
#define OFF_HHI (OFF_WLO + 64 * LDW * 2)
#define OFF_HLO (OFF_HHI + 32 * LDH * 2)
#define OFF_GT  (OFF_HLO + 32 * LDH * 2)
#define LSTM_SMEM (OFF_GT + 64 * LDC * 4)

__global__ __launch_bounds__(256, 1) void lstm_wmma(const float* __restrict__ Whh)
{
    extern __shared__ char sm[];
    __nv_bfloat16* w_hi = (__nv_bfloat16*)(sm + OFF_WHI);
    __nv_bfloat16* w_lo = (__nv_bfloat16*)(sm + OFF_WLO);
    __nv_bfloat16* h_hi = (__nv_bfloat16*)(sm + OFF_HHI);
    __nv_bfloat16* h_lo = (__nv_bfloat16*)(sm + OFF_HLO);
    float*         gt   = (float*)(sm + OFF_GT);

    const int bid = blockIdx.x;
    const int cg  = bid >> 2;
    const int bg  = bid & 3;
    const int t   = threadIdx.x;
    const int wid = t >> 5;
    const int mt  = wid >> 1;
    const int nt  = wid & 1;

    {
        const int p   = t >> 2;
        const int ks  = (t & 3) * 128;
        const int j   = (p >> 4) * H_ + cg * 16 + (p & 15);
        const float* src = Whh + (size_t)j * H_ + ks;
        __nv_bfloat16* dh = w_hi + p * LDW + ks;
        __nv_bfloat16* dl = w_lo + p * LDW + ks;
#pragma unroll 8
        for (int i = 0; i < 128; i += 4) {
            float4 v = *(const float4*)(src + i);
            __nv_bfloat162 h0 = __floats2bfloat162_rn(v.x, v.y);
            __nv_bfloat162 h1 = __floats2bfloat162_rn(v.z, v.w);
            __nv_bfloat162 l0 = __floats2bfloat162_rn(v.x - __bfloat162float(h0.x),
                                                      v.y - __bfloat162float(h0.y));
            __nv_bfloat162 l1 = __floats2bfloat162_rn(v.z - __bfloat162float(h1.x),
                                                      v.w - __bfloat162float(h1.y));
            *(uint32_t*)(dh + i)     = *(uint32_t*)&h0;
            *(uint32_t*)(dh + i + 2) = *(uint32_t*)&h1;
            *(uint32_t*)(dl + i)     = *(uint32_t*)&l0;
            *(uint32_t*)(dl + i + 2) = *(uint32_t*)&l1;
        }
    }

    const int cc0 = 2 * t,     cc1 = 2 * t + 1;
    const int nn0 = cc0 >> 5,  bl0 = cc0 & 31;
    const int nn1 = cc1 >> 5,  bl1 = cc1 & 31;
    float creg0 = 0.0f, creg1 = 0.0f;
    const size_t gb0 = (size_t)(bg * 32 + bl0) * G4 + cg * 16 + nn0;
    const size_t gb1 = (size_t)(bg * 32 + bl1) * G4 + cg * 16 + nn1;

    __syncthreads();

    for (int s = 0; s < S_; ++s) {
        const float* Gs = g_G + (size_t)s * (B_ * G4);
        float pg0[4], pg1[4];
#pragma unroll
        for (int g = 0; g < 4; g++) {
            pg0[g] = Gs[gb0 + g * H_];
            pg1[g] = Gs[gb1 + g * H_];
        }

        {
            const float* h_in = g_h[s & 1];
            const int row = t >> 3;
            const int ks  = (t & 7) * 64;
            const float* src = h_in + (size_t)(bg * 32 + row) * H_ + ks;
            __nv_bfloat16* dh = h_hi + row * LDH + ks;
            __nv_bfloat16* dl = h_lo + row * LDH + ks;
#pragma unroll 4
            for (int i = 0; i < 64; i += 4) {
                float4 v = *(const float4*)(src + i);
                __nv_bfloat162 h0 = __floats2bfloat162_rn(v.x, v.y);
                __nv_bfloat162 h1 = __floats2bfloat162_rn(v.z, v.w);
                __nv_bfloat162 l0 = __floats2bfloat162_rn(v.x - __bfloat162float(h0.x),
                                                          v.y - __bfloat162float(h0.y));
                __nv_bfloat162 l1 = __floats2bfloat162_rn(v.z - __bfloat162float(h1.x),
                                                          v.w - __bfloat162float(h1.y));
                *(uint32_t*)(dh + i)     = *(uint32_t*)&h0;
                *(uint32_t*)(dh + i + 2) = *(uint32_t*)&h1;
                *(uint32_t*)(dl + i)     = *(uint32_t*)&l0;
                *(uint32_t*)(dl + i + 2) = *(uint32_t*)&l1;
            }
        }
        __syncthreads();

        {
            wmma::fragment<wmma::accumulator, 16, 16, 16, float> acc;
            wmma::fill_fragment(acc, 0.0f);
            const __nv_bfloat16* wbase_h = w_hi + (mt * 16) * LDW;
            const __nv_bfloat16* wbase_l = w_lo + (mt * 16) * LDW;
            const __nv_bfloat16* hbase_h = h_hi + (nt * 16) * LDH;
            const __nv_bfloat16* hbase_l = h_lo + (nt * 16) * LDH;
#pragma unroll 4
            for (int k = 0; k < 32; k++) {
                wmma::fragment<wmma::matrix_a, 16, 16, 16, __nv_bfloat16, wmma::row_major> a_h, a_l;
                wmma::fragment<wmma::matrix_b, 16, 16, 16, __nv_bfloat16, wmma::col_major> b_h, b_l;
                wmma::load_matrix_sync(a_h, wbase_h + k * 16, LDW);
                wmma::load_matrix_sync(a_l, wbase_l + k * 16, LDW);
                wmma::load_matrix_sync(b_h, hbase_h + k * 16, LDH);
                wmma::load_matrix_sync(b_l, hbase_l + k * 16, LDH);
                wmma::mma_sync(acc, a_h, b_h, acc);
                wmma::mma_sync(acc, a_h, b_l, acc);
                wmma::mma_sync(acc, a_l, b_h, acc);
            }
            wmma::store_matrix_sync(gt + (mt * 16) * LDC + nt * 16, acc, LDC,
                                    wmma::mem_row_major);
        }
        __syncthreads();

        float* h_out = g_h[(s + 1) & 1];
        {
            float gi = pg0[0] + gt[(0 * 16 + nn0) * LDC + bl0];
            float gf = pg0[1] + gt[(1 * 16 + nn0) * LDC + bl0];
            float gg = pg0[2] + gt[(2 * 16 + nn0) * LDC + bl0];
            float go = pg0[3] + gt[(3 * 16 + nn0) * LDC + bl0];
            float si = 1.0f / (1.0f + __expf(-gi));
            float sf = 1.0f / (1.0f + __expf(-gf));
            float tg = tanhf(gg);
            float so = 1.0f / (1.0f + __expf(-go));
            creg0 = sf * creg0 + si * tg;
            h_out[(size_t)(bg * 32 + bl0) * H_ + cg * 16 + nn0] = so * tanhf(creg0);
        }
        {
            float gi = pg1[0] + gt[(0 * 16 + nn1) * LDC + bl1];
            float gf = pg1[1] + gt[(1 * 16 + nn1) * LDC + bl1];
            float gg = pg1[2] + gt[(2 * 16 + nn1) * LDC + bl1];
            float go = pg1[3] + gt[(3 * 16 + nn1) * LDC + bl1];
            float si = 1.0f / (1.0f + __expf(-gi));
            float sf = 1.0f / (1.0f + __expf(-gf));
            float tg = tanhf(gg);
            float so = 1.0f / (1.0f + __expf(-go));
            creg1 = sf * creg1 + si * tg;
            h_out[(size_t)(bg * 32 + bl1) * H_ + cg * 16 + nn1] = so * tanhf(creg1);
        }

        __threadfence();
        __syncthreads();
        if (t == 0) {
            int old = atomicAdd(&g_cnt, 1);
            if (old == NBLK - 1) {
                atomicExch(&g_cnt, 0);
                __threadfence();
                g_gen = s + 1;
            } else {
                while (g_gen <= s) { }
                __threadfence();
            }
        }
        __syncthreads();
    }
}

// ---------------------------------------------------------------------------
// Final reduction
// ---------------------------------------------------------------------------
__global__ __launch_bounds__(1024) void reduce_h(float* __restrict__ out) {
    __shared__ float red[1024];
    const int t = threadIdx.x;
    float s = 0.0f;
    for (int i = t; i < B_ * H_; i += 1024) s += g_h[0][i];
    red[t] = s;
    __syncthreads();
    for (int off = 512; off > 0; off >>= 1) {
        if (t < off) red[t] += red[t + off];
        __syncthreads();
    }
    if (t == 0) out[0] = red[0];
}

// ---------------------------------------------------------------------------
// kernel_launch
// ---------------------------------------------------------------------------
extern "C" void kernel_launch(void* const* d_in, const int* in_sizes, int n_in,
                              void* d_out, int out_size) {
    const float* x    = (const float*)d_in[0];
    const float* w_ih = (const float*)d_in[1];
    const float* w_hh = (const float*)d_in[2];
    const float* b_ih = (const float*)d_in[3];
    const float* b_hh = (const float*)d_in[4];
    float* out = (float*)d_out;

    static_assert(LSTM_SMEM <= 227 * 1024, "smem overflow (lstm)");
    static_assert(GEMM_SMEM <= 227 * 1024, "smem overflow (gemm)");
    cudaFuncSetAttribute(lstm_wmma,
                         cudaFuncAttributeMaxDynamicSharedMemorySize,
                         LSTM_SMEM);
    cudaFuncSetAttribute(gemm_fp16,
                         cudaFuncAttributeMaxDynamicSharedMemorySize,
                         GEMM_SMEM);

    init_state<<<(B_ * H_ + 255) / 256, 256>>>();
    fill_bias<<<(G4 + 255) / 256, 256>>>(b_ih, b_hh);

    dim3 ggrid(G4 / 256, M_TOT / 128);   // (8, 256) = 2048 CTAs
    gemm_fp16<<<ggrid, 256, GEMM_SMEM>>>(x, w_ih);

    lstm_wmma<<<NBLK, 256, LSTM_SMEM>>>(w_hh);

    reduce_h<<<1, 1024>>>(out);
}

// round 14
// speedup vs baseline: 2.1337x; 1.4282x over previous
#include <cuda_runtime.h>
#include <cuda_bf16.h>
#include <cuda_fp16.h>
#include <math.h>
#include <stdint.h>
#include <mma.h>

using namespace nvcuda;

// Problem constants
#define S_   256
#define B_   128
#define I_   1024
#define H_   512
#define G4  (4 * H_)            // 2048 gate columns
#define M_TOT (S_ * B_)         // 32768 rows of the input GEMM
#define NBLK 128

// ---------------------------------------------------------------------------
// Device scratch — statics held at the proven ~269 MB budget.
// ---------------------------------------------------------------------------
__device__ float g_G[(size_t)M_TOT * G4];     // x@w_ih^T + bias  (268 MB)
__device__ float g_h[2][B_ * H_];             // double-buffered hidden state
__device__ int            g_cnt;              // grid barrier arrive counter
__device__ volatile int   g_gen;              // grid barrier generation
__device__ float g_bias_rep[16 * G4];         // bias replicated over 16 rows

// ---------------------------------------------------------------------------
// Init: zero h0 and barrier state
// ---------------------------------------------------------------------------
__global__ void init_state() {
    int i = blockIdx.x * blockDim.x + threadIdx.x;
    if (i < B_ * H_) g_h[0][i] = 0.0f;
    if (i == 0) { g_cnt = 0; g_gen = 0; }
}

// ---------------------------------------------------------------------------
// Fill 16-row replicated bias strip (loaded as wmma C fragment)
// ---------------------------------------------------------------------------
__global__ void fill_bias(const float* __restrict__ bih,
                          const float* __restrict__ bhh) {
    int c = blockIdx.x * blockDim.x + threadIdx.x;
    if (c < G4) {
        float v = bih[c] + bhh[c];
#pragma unroll
        for (int r = 0; r < 16; r++) g_bias_rep[r * G4 + c] = v;
    }
}

// ---------------------------------------------------------------------------
// pack fp32x8 -> fp16x8, one uint4 store
// ---------------------------------------------------------------------------
__device__ __forceinline__ void half_store8(
    __half* __restrict__ dst, float4 v0, float4 v1)
{
    __half2 h0 = __floats2half2_rn(v0.x, v0.y);
    __half2 h1 = __floats2half2_rn(v0.z, v0.w);
    __half2 h2 = __floats2half2_rn(v1.x, v1.y);
    __half2 h3 = __floats2half2_rn(v1.z, v1.w);
    *(uint4*)dst = make_uint4(*(uint32_t*)&h0, *(uint32_t*)&h1,
                              *(uint32_t*)&h2, *(uint32_t*)&h3);
}

// ---------------------------------------------------------------------------
// Phase 1: G = X @ W_ih^T + bias — EXACT R10 kernel (known 2.1 ms, passing).
// ---------------------------------------------------------------------------
#define LDS_T 24
#define NIT   (I_ / 16)     // 64 k-iterations

__global__ __launch_bounds__(256, 2) void gemm_fp16(
    const float* __restrict__ X,
    const float* __restrict__ W)
{
    __shared__ __half sA[2][128 * LDS_T];
    __shared__ __half sB[2][128 * LDS_T];

    const int t   = threadIdx.x;
    const int wid = t >> 5;
    const int m0  = blockIdx.y * 128;
    const int n0  = blockIdx.x * 128;
    const int wr  = wid >> 2;
    const int wc  = wid & 3;

    wmma::fragment<wmma::accumulator, 16, 16, 16, float> acc[4][2];
#pragma unroll
    for (int mt = 0; mt < 4; mt++)
#pragma unroll
        for (int nt = 0; nt < 2; nt++)
            wmma::load_matrix_sync(acc[mt][nt],
                g_bias_rep + n0 + wc * 32 + nt * 16, G4, wmma::mem_row_major);

    const int lrow  = t >> 1;
    const int lhalf = (t & 1) * 8;
    const float* gA = X + (size_t)(m0 + lrow) * I_ + lhalf;
    const float* gB = W + (size_t)(n0 + lrow) * I_ + lhalf;
    const int soff = lrow * LDS_T + lhalf;

    float4 a0 = *(const float4*)(gA);
    float4 a1 = *(const float4*)(gA + 4);
    float4 b0 = *(const float4*)(gB);
    float4 b1 = *(const float4*)(gB + 4);
    half_store8(&sA[0][soff], a0, a1);
    half_store8(&sB[0][soff], b0, b1);
    a0 = *(const float4*)(gA + 16);
    a1 = *(const float4*)(gA + 20);
    b0 = *(const float4*)(gB + 16);
    b1 = *(const float4*)(gB + 20);
    __syncthreads();

    for (int it = 0; it < NIT; ++it) {
        const int cur = it & 1;

        if (it < NIT - 1) {
            half_store8(&sA[cur ^ 1][soff], a0, a1);
            half_store8(&sB[cur ^ 1][soff], b0, b1);
            if (it < NIT - 2) {
                const float* pa = gA + (it + 2) * 16;
                const float* pb = gB + (it + 2) * 16;
                a0 = *(const float4*)(pa);
                a1 = *(const float4*)(pa + 4);
                b0 = *(const float4*)(pb);
                b1 = *(const float4*)(pb + 4);
            }
        }

        wmma::fragment<wmma::matrix_a, 16, 16, 16, __half, wmma::row_major> af[4];
        wmma::fragment<wmma::matrix_b, 16, 16, 16, __half, wmma::col_major> bf[2];
#pragma unroll
        for (int mt = 0; mt < 4; mt++)
            wmma::load_matrix_sync(af[mt], &sA[cur][(wr * 64 + mt * 16) * LDS_T], LDS_T);
#pragma unroll
        for (int nt = 0; nt < 2; nt++)
            wmma::load_matrix_sync(bf[nt], &sB[cur][(wc * 32 + nt * 16) * LDS_T], LDS_T);
#pragma unroll
        for (int mt = 0; mt < 4; mt++)
#pragma unroll
            for (int nt = 0; nt < 2; nt++)
                wmma::mma_sync(acc[mt][nt], af[mt], bf[nt], acc[mt][nt]);
        __syncthreads();
    }

#pragma unroll
    for (int mt = 0; mt < 4; mt++)
#pragma unroll
        for (int nt = 0; nt < 2; nt++)
            wmma::store_matrix_sync(
                g_G + (size_t)(m0 + wr * 64 + mt * 16) * G4 + n0 + wc * 32 + nt * 16,
                acc[mt][nt], G4, wmma::mem_row_major);
}

// ---------------------------------------------------------------------------
// Phase 2: persistent LSTM recurrence — single-term fp16 (32 wmma/warp/step).
// Gate noise from fp16 w_hh & h: ~5e-5/step, 12x below the x-gemm term.
// Structure otherwise identical to the verified R8/R10 kernel.
// ---------------------------------------------------------------------------
#define LDW 520                 // half row stride
#define LDH 520
#define LDC 36
#define OFF_W   0
#define OFF_H   (OFF_W + 64 * LDW * 2)          // 66560
#define OFF_GT  (OFF_H + 32 * LDH * 2)          // 99840
#define LSTM_SMEM (OFF_GT + 64 * LDC * 4)       // 109056 bytes

__global__ __launch_bounds__(256, 1) void lstm_wmma(const float* __restrict__ Whh)
{
    extern __shared__ char sm[];
    __half* s_w = (__half*)(sm + OFF_W);
    __half* s_h = (__half*)(sm + OFF_H);
    float*  gt  = (float*)(sm + OFF_GT);

    const int bid = blockIdx.x;
    const int cg  = bid >> 2;
    const int bg  = bid & 3;
    const int t   = threadIdx.x;
    const int wid = t >> 5;
    const int mt  = wid >> 1;
    const int nt  = wid & 1;

    // ---- stage W tile (64 x 512) as single fp16, once ----
    {
        const int p   = t >> 2;
        const int ks  = (t & 3) * 128;
        const int j   = (p >> 4) * H_ + cg * 16 + (p & 15);
        const float* src = Whh + (size_t)j * H_ + ks;
        __half* dst = s_w + p * LDW + ks;
#pragma unroll 8
        for (int i = 0; i < 128; i += 8) {
            float4 v0 = *(const float4*)(src + i);
            float4 v1 = *(const float4*)(src + i + 4);
            half_store8(dst + i, v0, v1);
        }
    }

    const int cc0 = 2 * t,     cc1 = 2 * t + 1;
    const int nn0 = cc0 >> 5,  bl0 = cc0 & 31;
    const int nn1 = cc1 >> 5,  bl1 = cc1 & 31;
    float creg0 = 0.0f, creg1 = 0.0f;
    const size_t gb0 = (size_t)(bg * 32 + bl0) * G4 + cg * 16 + nn0;
    const size_t gb1 = (size_t)(bg * 32 + bl1) * G4 + cg * 16 + nn1;

    __syncthreads();

    for (int s = 0; s < S_; ++s) {
        // ---- prefetch this step's G gate values ----
        const float* Gs = g_G + (size_t)s * (B_ * G4);
        float pg0[4], pg1[4];
#pragma unroll
        for (int g = 0; g < 4; g++) {
            pg0[g] = Gs[gb0 + g * H_];
            pg1[g] = Gs[gb1 + g * H_];
        }

        // ---- stage h tile (32 x 512) as single fp16 ----
        {
            const float* h_in = g_h[s & 1];
            const int row = t >> 3;
            const int ks  = (t & 7) * 64;
            const float* src = h_in + (size_t)(bg * 32 + row) * H_ + ks;
            __half* dst = s_h + row * LDH + ks;
#pragma unroll 4
            for (int i = 0; i < 64; i += 8) {
                float4 v0 = *(const float4*)(src + i);
                float4 v1 = *(const float4*)(src + i + 4);
                half_store8(dst + i, v0, v1);
            }
        }
        __syncthreads();

        // ---- recurrent GEMM: 32 wmma per warp ----
        {
            wmma::fragment<wmma::accumulator, 16, 16, 16, float> acc;
            wmma::fill_fragment(acc, 0.0f);
            const __half* wb = s_w + (mt * 16) * LDW;
            const __half* hb = s_h + (nt * 16) * LDH;
#pragma unroll 8
            for (int k = 0; k < 32; k++) {
                wmma::fragment<wmma::matrix_a, 16, 16, 16, __half, wmma::row_major> a;
                wmma::fragment<wmma::matrix_b, 16, 16, 16, __half, wmma::col_major> b;
                wmma::load_matrix_sync(a, wb + k * 16, LDW);
                wmma::load_matrix_sync(b, hb + k * 16, LDH);
                wmma::mma_sync(acc, a, b, acc);
            }
            wmma::store_matrix_sync(gt + (mt * 16) * LDC + nt * 16, acc, LDC,
                                    wmma::mem_row_major);
        }
        __syncthreads();

        // ---- pointwise LSTM update (2 cells per thread) ----
        float* h_out = g_h[(s + 1) & 1];
        {
            float gi = pg0[0] + gt[(0 * 16 + nn0) * LDC + bl0];
            float gf = pg0[1] + gt[(1 * 16 + nn0) * LDC + bl0];
            float gg = pg0[2] + gt[(2 * 16 + nn0) * LDC + bl0];
            float go = pg0[3] + gt[(3 * 16 + nn0) * LDC + bl0];
            float si = 1.0f / (1.0f + __expf(-gi));
            float sf = 1.0f / (1.0f + __expf(-gf));
            float tg = tanhf(gg);
            float so = 1.0f / (1.0f + __expf(-go));
            creg0 = sf * creg0 + si * tg;
            h_out[(size_t)(bg * 32 + bl0) * H_ + cg * 16 + nn0] = so * tanhf(creg0);
        }
        {
            float gi = pg1[0] + gt[(0 * 16 + nn1) * LDC + bl1];
            float gf = pg1[1] + gt[(1 * 16 + nn1) * LDC + bl1];
            float gg = pg1[2] + gt[(2 * 16 + nn1) * LDC + bl1];
            float go = pg1[3] + gt[(3 * 16 + nn1) * LDC + bl1];
            float si = 1.0f / (1.0f + __expf(-gi));
            float sf = 1.0f / (1.0f + __expf(-gf));
            float tg = tanhf(gg);
            float so = 1.0f / (1.0f + __expf(-go));
            creg1 = sf * creg1 + si * tg;
            h_out[(size_t)(bg * 32 + bl1) * H_ + cg * 16 + nn1] = so * tanhf(creg1);
        }

        // ---- grid barrier ----
        __threadfence();
        __syncthreads();
        if (t == 0) {
            int old = atomicAdd(&g_cnt, 1);
            if (old == NBLK - 1) {
                atomicExch(&g_cnt, 0);
                __threadfence();
                g_gen = s + 1;
            } else {
                while (g_gen <= s) { }
                __threadfence();
            }
        }
        __syncthreads();
    }
}

// ---------------------------------------------------------------------------
// Final reduction
// ---------------------------------------------------------------------------
__global__ __launch_bounds__(1024) void reduce_h(float* __restrict__ out) {
    __shared__ float red[1024];
    const int t = threadIdx.x;
    float s = 0.0f;
    for (int i = t; i < B_ * H_; i += 1024) s += g_h[0][i];
    red[t] = s;
    __syncthreads();
    for (int off = 512; off > 0; off >>= 1) {
        if (t < off) red[t] += red[t + off];
        __syncthreads();
    }
    if (t == 0) out[0] = red[0];
}

// ---------------------------------------------------------------------------
// kernel_launch
// ---------------------------------------------------------------------------
extern "C" void kernel_launch(void* const* d_in, const int* in_sizes, int n_in,
                              void* d_out, int out_size) {
    const float* x    = (const float*)d_in[0];
    const float* w_ih = (const float*)d_in[1];
    const float* w_hh = (const float*)d_in[2];
    const float* b_ih = (const float*)d_in[3];
    const float* b_hh = (const float*)d_in[4];
    float* out = (float*)d_out;

    static_assert(LSTM_SMEM <= 227 * 1024, "smem overflow (lstm)");
    cudaFuncSetAttribute(lstm_wmma,
                         cudaFuncAttributeMaxDynamicSharedMemorySize,
                         LSTM_SMEM);

    init_state<<<(B_ * H_ + 255) / 256, 256>>>();
    fill_bias<<<(G4 + 255) / 256, 256>>>(b_ih, b_hh);

    dim3 ggrid(G4 / 128, M_TOT / 128);   // (16, 256)
    gemm_fp16<<<ggrid, 256>>>(x, w_ih);

    lstm_wmma<<<NBLK, 256, LSTM_SMEM>>>(w_hh);

    reduce_h<<<1, 1024>>>(out);
}

// round 17
// speedup vs baseline: 2.3264x; 1.0903x over previous
#include <cuda_runtime.h>
#include <cuda_bf16.h>
#include <cuda_fp16.h>
#include <math.h>
#include <stdint.h>
#include <mma.h>

using namespace nvcuda;

// Problem constants
#define S_   256
#define B_   128
#define I_   1024
#define H_   512
#define G4  (4 * H_)            // 2048 gate columns
#define M_TOT (S_ * B_)         // 32768 rows of the input GEMM
#define NBLK 128

// ---------------------------------------------------------------------------
// Device scratch. RULE (hard-won): NEVER pass these symbols as host-side
// kernel arguments — on GB300/ATS the host shadow symbol silently absorbs
// the writes. Reference them INSIDE kernels only.
// ---------------------------------------------------------------------------
__device__ __half g_G16[(size_t)M_TOT * G4];  // gates, fp16 (134 MB)
__device__ __half g_x16[(size_t)M_TOT * I_];  // fp16 X (67 MB)
__device__ __half g_w16[(size_t)G4 * I_];     // fp16 W_ih (4 MB)
__device__ float g_h[2][B_ * H_];             // double-buffered hidden state
__device__ int            g_cnt;              // grid barrier arrive counter
__device__ volatile int   g_gen;              // grid barrier generation
__device__ float g_bias_rep[16 * G4];         // bias replicated over 16 rows

// ---------------------------------------------------------------------------
// Init: zero h0 and barrier state
// ---------------------------------------------------------------------------
__global__ void init_state() {
    int i = blockIdx.x * blockDim.x + threadIdx.x;
    if (i < B_ * H_) g_h[0][i] = 0.0f;
    if (i == 0) { g_cnt = 0; g_gen = 0; }
}

// ---------------------------------------------------------------------------
// Fill 16-row replicated bias strip (loaded as wmma C fragment)
// ---------------------------------------------------------------------------
__global__ void fill_bias(const float* __restrict__ bih,
                          const float* __restrict__ bhh) {
    int c = blockIdx.x * blockDim.x + threadIdx.x;
    if (c < G4) {
        float v = bih[c] + bhh[c];
#pragma unroll
        for (int r = 0; r < 16; r++) g_bias_rep[r * G4 + c] = v;
    }
}

// ---------------------------------------------------------------------------
// fp32 -> fp16 converters. Destination statics referenced IN-KERNEL
// (passing them as host args hits the ATS shadow-symbol trap).
// ---------------------------------------------------------------------------
__global__ __launch_bounds__(256) void conv_x(const float* __restrict__ src) {
    const int n4 = M_TOT * I_ / 4;
    for (int i = blockIdx.x * blockDim.x + threadIdx.x; i < n4;
         i += gridDim.x * blockDim.x) {
        float4 v = *(const float4*)(src + (size_t)i * 4);
        __half2 a = __floats2half2_rn(v.x, v.y);
        __half2 b = __floats2half2_rn(v.z, v.w);
        *(uint32_t*)(g_x16 + (size_t)i * 4)     = *(uint32_t*)&a;
        *(uint32_t*)(g_x16 + (size_t)i * 4 + 2) = *(uint32_t*)&b;
    }
}

__global__ __launch_bounds__(256) void conv_w(const float* __restrict__ src) {
    const int n4 = G4 * I_ / 4;
    for (int i = blockIdx.x * blockDim.x + threadIdx.x; i < n4;
         i += gridDim.x * blockDim.x) {
        float4 v = *(const float4*)(src + (size_t)i * 4);
        __half2 a = __floats2half2_rn(v.x, v.y);
        __half2 b = __floats2half2_rn(v.z, v.w);
        *(uint32_t*)(g_w16 + (size_t)i * 4)     = *(uint32_t*)&a;
        *(uint32_t*)(g_w16 + (size_t)i * 4 + 2) = *(uint32_t*)&b;
    }
}

// ---------------------------------------------------------------------------
// cp.async helpers
// ---------------------------------------------------------------------------
__device__ __forceinline__ void cpa16(uint32_t dst, const void* src) {
    asm volatile("cp.async.ca.shared.global [%0], [%1], 16;"
                 :: "r"(dst), "l"(src));
}
#define CP_COMMIT() asm volatile("cp.async.commit_group;" ::: "memory")
#define CP_WAIT1()  asm volatile("cp.async.wait_group 1;" ::: "memory")

// ---------------------------------------------------------------------------
// Phase 1: G16 = fp16( X16 @ W16^T + bias ), fp16 WMMA, cp.async, BK=32.
// 128x128 block tile, 8 warps (2m x 4n), 4x2 m16n16k16 tiles/warp,
// 16 mma per warp-iter, 32 iterations, 2 CTAs/SM.
// ---------------------------------------------------------------------------
#define BK   32
#define LDSF 40                 // half row stride (80B, padded)
#define NI   (I_ / BK)          // 32
#define ESCR 20                 // epilogue scratch stride in floats (80B, 16B-aligned)

__global__ __launch_bounds__(256, 2) void gemm_fp16()
{
    __shared__ __half sA[2][128 * LDSF];
    __shared__ __half sB[2][128 * LDSF];

    const int t    = threadIdx.x;
    const int wid  = t >> 5;
    const int lane = t & 31;
    const int m0  = blockIdx.y * 128;
    const int n0  = blockIdx.x * 128;
    const int wr  = wid >> 2;
    const int wc  = wid & 3;

    wmma::fragment<wmma::accumulator, 16, 16, 16, float> acc[4][2];
#pragma unroll
    for (int mt = 0; mt < 4; mt++)
#pragma unroll
        for (int nt = 0; nt < 2; nt++)
            wmma::load_matrix_sync(acc[mt][nt],
                g_bias_rep + n0 + wc * 32 + nt * 16, G4, wmma::mem_row_major);

    // staging: thread t owns row = t>>1, halfs [sg, sg+16) of each 32-half chunk
    const int row = t >> 1;
    const int sg  = (t & 1) * 16;
    const __half* gA16 = g_x16 + (size_t)(m0 + row) * I_ + sg;
    const __half* gB16 = g_w16 + (size_t)(n0 + row) * I_ + sg;
    const uint32_t daBase[2] = {
        (uint32_t)__cvta_generic_to_shared(&sA[0][row * LDSF + sg]),
        (uint32_t)__cvta_generic_to_shared(&sA[1][row * LDSF + sg]) };
    const uint32_t dbBase[2] = {
        (uint32_t)__cvta_generic_to_shared(&sB[0][row * LDSF + sg]),
        (uint32_t)__cvta_generic_to_shared(&sB[1][row * LDSF + sg]) };

    // prologue: chunks 0 and 1 in flight
#pragma unroll
    for (int p = 0; p < 2; p++) {
        cpa16(daBase[p],      gA16 + p * BK);
        cpa16(daBase[p] + 16, gA16 + p * BK + 8);
        cpa16(dbBase[p],      gB16 + p * BK);
        cpa16(dbBase[p] + 16, gB16 + p * BK + 8);
        CP_COMMIT();
    }
    CP_WAIT1();          // chunk 0 arrived
    __syncthreads();

    for (int it = 0; it < NI; ++it) {
        const int cur = it & 1;

        // compute on buffer cur (chunk it): 2 x k16, 16 wmma total
#pragma unroll
        for (int kk = 0; kk < 2; kk++) {
            wmma::fragment<wmma::matrix_a, 16, 16, 16, __half, wmma::row_major> af[4];
            wmma::fragment<wmma::matrix_b, 16, 16, 16, __half, wmma::col_major> bf[2];
#pragma unroll
            for (int mt = 0; mt < 4; mt++)
                wmma::load_matrix_sync(af[mt],
                    &sA[cur][(wr * 64 + mt * 16) * LDSF + kk * 16], LDSF);
#pragma unroll
            for (int nt = 0; nt < 2; nt++)
                wmma::load_matrix_sync(bf[nt],
                    &sB[cur][(wc * 32 + nt * 16) * LDSF + kk * 16], LDSF);
#pragma unroll
            for (int mt = 0; mt < 4; mt++)
#pragma unroll
                for (int nt = 0; nt < 2; nt++)
                    wmma::mma_sync(acc[mt][nt], af[mt], bf[nt], acc[mt][nt]);
        }
        __syncthreads();                       // all warps done reading cur

        if (it + 2 < NI) {                     // refill cur with chunk it+2
            const int k0 = (it + 2) * BK;
            cpa16(daBase[cur],      gA16 + k0);
            cpa16(daBase[cur] + 16, gA16 + k0 + 8);
            cpa16(dbBase[cur],      gB16 + k0);
            cpa16(dbBase[cur] + 16, gB16 + k0 + 8);
            CP_COMMIT();
        }
        CP_WAIT1();                            // chunk it+1 arrived
        __syncthreads();
    }

    // ---- epilogue: acc (fp32) -> fp16 G16 via per-warp smem scratch ----
    // ESCR=20 floats (80B) keeps every scratch row 16B-aligned.
    __syncthreads();                           // safe to reuse sA as scratch
    float* scratch = (float*)&sA[0][0] + wid * 16 * ESCR;
    const int erow = lane >> 1;
    const int ecol = (lane & 1) * 8;
#pragma unroll
    for (int mt = 0; mt < 4; mt++)
#pragma unroll
        for (int nt = 0; nt < 2; nt++) {
            wmma::store_matrix_sync(scratch, acc[mt][nt], ESCR, wmma::mem_row_major);
            __syncwarp();
            const float* srow = scratch + erow * ESCR + ecol;
            float4 v0 = *(const float4*)(srow);
            float4 v1 = *(const float4*)(srow + 4);
            __half2 a = __floats2half2_rn(v0.x, v0.y);
            __half2 b = __floats2half2_rn(v0.z, v0.w);
            __half2 c = __floats2half2_rn(v1.x, v1.y);
            __half2 d = __floats2half2_rn(v1.z, v1.w);
            __half* dst = g_G16 + (size_t)(m0 + wr * 64 + mt * 16 + erow) * G4
                                 + n0 + wc * 32 + nt * 16 + ecol;
            *(uint4*)dst = make_uint4(*(uint32_t*)&a, *(uint32_t*)&b,
                                      *(uint32_t*)&c, *(uint32_t*)&d);
            __syncwarp();
        }
}

// ---------------------------------------------------------------------------
// Phase 2: persistent LSTM recurrence (R14 verbatim; G reads fp16).
// ---------------------------------------------------------------------------
__device__ __forceinline__ void half_store8(
    __half* __restrict__ dst, float4 v0, float4 v1)
{
    __half2 h0 = __floats2half2_rn(v0.x, v0.y);
    __half2 h1 = __floats2half2_rn(v0.z, v0.w);
    __half2 h2 = __floats2half2_rn(v1.x, v1.y);
    __half2 h3 = __floats2half2_rn(v1.z, v1.w);
    *(uint4*)dst = make_uint4(*(uint32_t*)&h0, *(uint32_t*)&h1,
                              *(uint32_t*)&h2, *(uint32_t*)&h3);
}

#define LDW 520
#define LDH 520
#define LDC 36
#define OFF_W   0
#define OFF_H   (OFF_W + 64 * LDW * 2)
#define OFF_GT  (OFF_H + 32 * LDH * 2)
#define LSTM_SMEM (OFF_GT + 64 * LDC * 4)

__global__ __launch_bounds__(256, 1) void lstm_wmma(const float* __restrict__ Whh)
{
    extern __shared__ char sm[];
    __half* s_w = (__half*)(sm + OFF_W);
    __half* s_h = (__half*)(sm + OFF_H);
    float*  gt  = (float*)(sm + OFF_GT);

    const int bid = blockIdx.x;
    const int cg  = bid >> 2;
    const int bg  = bid & 3;
    const int t   = threadIdx.x;
    const int wid = t >> 5;
    const int mt  = wid >> 1;
    const int nt  = wid & 1;

    {
        const int p   = t >> 2;
        const int ks  = (t & 3) * 128;
        const int j   = (p >> 4) * H_ + cg * 16 + (p & 15);
        const float* src = Whh + (size_t)j * H_ + ks;
        __half* dst = s_w + p * LDW + ks;
#pragma unroll 8
        for (int i = 0; i < 128; i += 8) {
            float4 v0 = *(const float4*)(src + i);
            float4 v1 = *(const float4*)(src + i + 4);
            half_store8(dst + i, v0, v1);
        }
    }

    const int cc0 = 2 * t,     cc1 = 2 * t + 1;
    const int nn0 = cc0 >> 5,  bl0 = cc0 & 31;
    const int nn1 = cc1 >> 5,  bl1 = cc1 & 31;
    float creg0 = 0.0f, creg1 = 0.0f;
    const size_t gb0 = (size_t)(bg * 32 + bl0) * G4 + cg * 16 + nn0;
    const size_t gb1 = (size_t)(bg * 32 + bl1) * G4 + cg * 16 + nn1;

    __syncthreads();

    for (int s = 0; s < S_; ++s) {
        const __half* Gs = g_G16 + (size_t)s * (B_ * G4);
        float pg0[4], pg1[4];
#pragma unroll
        for (int g = 0; g < 4; g++) {
            pg0[g] = __half2float(Gs[gb0 + g * H_]);
            pg1[g] = __half2float(Gs[gb1 + g * H_]);
        }

        {
            const float* h_in = g_h[s & 1];
            const int row = t >> 3;
            const int ks  = (t & 7) * 64;
            const float* src = h_in + (size_t)(bg * 32 + row) * H_ + ks;
            __half* dst = s_h + row * LDH + ks;
#pragma unroll 4
            for (int i = 0; i < 64; i += 8) {
                float4 v0 = *(const float4*)(src + i);
                float4 v1 = *(const float4*)(src + i + 4);
                half_store8(dst + i, v0, v1);
            }
        }
        __syncthreads();

        {
            wmma::fragment<wmma::accumulator, 16, 16, 16, float> acc;
            wmma::fill_fragment(acc, 0.0f);
            const __half* wb = s_w + (mt * 16) * LDW;
            const __half* hb = s_h + (nt * 16) * LDH;
#pragma unroll 8
            for (int k = 0; k < 32; k++) {
                wmma::fragment<wmma::matrix_a, 16, 16, 16, __half, wmma::row_major> a;
                wmma::fragment<wmma::matrix_b, 16, 16, 16, __half, wmma::col_major> b;
                wmma::load_matrix_sync(a, wb + k * 16, LDW);
                wmma::load_matrix_sync(b, hb + k * 16, LDH);
                wmma::mma_sync(acc, a, b, acc);
            }
            wmma::store_matrix_sync(gt + (mt * 16) * LDC + nt * 16, acc, LDC,
                                    wmma::mem_row_major);
        }
        __syncthreads();

        float* h_out = g_h[(s + 1) & 1];
        {
            float gi = pg0[0] + gt[(0 * 16 + nn0) * LDC + bl0];
            float gf = pg0[1] + gt[(1 * 16 + nn0) * LDC + bl0];
            float gg = pg0[2] + gt[(2 * 16 + nn0) * LDC + bl0];
            float go = pg0[3] + gt[(3 * 16 + nn0) * LDC + bl0];
            float si = 1.0f / (1.0f + __expf(-gi));
            float sf = 1.0f / (1.0f + __expf(-gf));
            float tg = tanhf(gg);
            float so = 1.0f / (1.0f + __expf(-go));
            creg0 = sf * creg0 + si * tg;
            h_out[(size_t)(bg * 32 + bl0) * H_ + cg * 16 + nn0] = so * tanhf(creg0);
        }
        {
            float gi = pg1[0] + gt[(0 * 16 + nn1) * LDC + bl1];
            float gf = pg1[1] + gt[(1 * 16 + nn1) * LDC + bl1];
            float gg = pg1[2] + gt[(2 * 16 + nn1) * LDC + bl1];
            float go = pg1[3] + gt[(3 * 16 + nn1) * LDC + bl1];
            float si = 1.0f / (1.0f + __expf(-gi));
            float sf = 1.0f / (1.0f + __expf(-gf));
            float tg = tanhf(gg);
            float so = 1.0f / (1.0f + __expf(-go));
            creg1 = sf * creg1 + si * tg;
            h_out[(size_t)(bg * 32 + bl1) * H_ + cg * 16 + nn1] = so * tanhf(creg1);
        }

        __threadfence();
        __syncthreads();
        if (t == 0) {
            int old = atomicAdd(&g_cnt, 1);
            if (old == NBLK - 1) {
                atomicExch(&g_cnt, 0);
                __threadfence();
                g_gen = s + 1;
            } else {
                while (g_gen <= s) { }
                __threadfence();
            }
        }
        __syncthreads();
    }
}

// ---------------------------------------------------------------------------
// Final reduction
// ---------------------------------------------------------------------------
__global__ __launch_bounds__(1024) void reduce_h(float* __restrict__ out) {
    __shared__ float red[1024];
    const int t = threadIdx.x;
    float s = 0.0f;
    for (int i = t; i < B_ * H_; i += 1024) s += g_h[0][i];
    red[t] = s;
    __syncthreads();
    for (int off = 512; off > 0; off >>= 1) {
        if (t < off) red[t] += red[t + off];
        __syncthreads();
    }
    if (t == 0) out[0] = red[0];
}

// ---------------------------------------------------------------------------
// kernel_launch
// ---------------------------------------------------------------------------
extern "C" void kernel_launch(void* const* d_in, const int* in_sizes, int n_in,
                              void* d_out, int out_size) {
    const float* x    = (const float*)d_in[0];
    const float* w_ih = (const float*)d_in[1];
    const float* w_hh = (const float*)d_in[2];
    const float* b_ih = (const float*)d_in[3];
    const float* b_hh = (const float*)d_in[4];
    float* out = (float*)d_out;

    static_assert(LSTM_SMEM <= 227 * 1024, "smem overflow (lstm)");
    cudaFuncSetAttribute(lstm_wmma,
                         cudaFuncAttributeMaxDynamicSharedMemorySize,
                         LSTM_SMEM);

    init_state<<<(B_ * H_ + 255) / 256, 256>>>();
    fill_bias<<<(G4 + 255) / 256, 256>>>(b_ih, b_hh);
    conv_x<<<4096, 256>>>(x);        // writes g_x16 in-kernel (NOT via host arg)
    conv_w<<<2048, 256>>>(w_ih);     // writes g_w16 in-kernel

    dim3 ggrid(G4 / 128, M_TOT / 128);   // (16, 256)
    gemm_fp16<<<ggrid, 256>>>();

    lstm_wmma<<<NBLK, 256, LSTM_SMEM>>>(w_hh);

    reduce_h<<<1, 1024>>>(out);
}